// round 9
// baseline (speedup 1.0000x reference)
#include <cuda_runtime.h>

#define NQ 12
#define NT 256
#define NL 2

typedef unsigned long long u64;

// ---- packed f32x2 helpers ----
__device__ __forceinline__ u64 pack2(float lo, float hi) {
    u64 v; asm("mov.b64 %0, {%1, %2};" : "=l"(v) : "f"(lo), "f"(hi)); return v;
}
__device__ __forceinline__ void unpack2(u64 v, float &lo, float &hi) {
    asm("mov.b64 {%0, %1}, %2;" : "=f"(lo), "=f"(hi) : "l"(v));
}
__device__ __forceinline__ u64 swap2(u64 v) {
    float lo, hi; unpack2(v, lo, hi); return pack2(hi, lo);
}
__device__ __forceinline__ u64 fma2(u64 a, u64 b, u64 c) {
    u64 d; asm("fma.rn.f32x2 %0, %1, %2, %3;" : "=l"(d) : "l"(a), "l"(b), "l"(c)); return d;
}
__device__ __forceinline__ u64 mul2(u64 a, u64 b) {
    u64 d; asm("mul.rn.f32x2 %0, %1, %2;" : "=l"(d) : "l"(a), "l"(b)); return d;
}
__device__ __forceinline__ u64 add2(u64 a, u64 b) {
    u64 d; asm("add.rn.f32x2 %0, %1, %2;" : "=l"(d) : "l"(a), "l"(b)); return d;
}

// State: X[j] = (re[j], re[j|8]), Y[j] = (im[j], im[j|8]), j = slot bits 0-2,
// packed half = slot bit 3. Slot s = wp*512 + lane*16 + r.
// Reference convention: qubit j <-> logical bit (11-j).

template<int B>
__device__ __forceinline__ void rx_low(u64 (&X)[8], u64 (&Y)[8],
                                       u64 c2, u64 s2, u64 sn2) {
    #pragma unroll
    for (int j = 0; j < 8; j++) {
        if (!((j >> B) & 1)) {
            const int j1 = j | (1 << B);
            u64 x0 = X[j], x1 = X[j1], y0 = Y[j], y1 = Y[j1];
            X[j]  = fma2(c2, x0, mul2(s2,  y1));
            X[j1] = fma2(c2, x1, mul2(s2,  y0));
            Y[j]  = fma2(c2, y0, mul2(sn2, x1));
            Y[j1] = fma2(c2, y1, mul2(sn2, x0));
        }
    }
}

__device__ __forceinline__ void rx_b3(u64 (&X)[8], u64 (&Y)[8],
                                      u64 c2, u64 s2, u64 sn2) {
    #pragma unroll
    for (int j = 0; j < 8; j++) {
        u64 sx = swap2(X[j]);
        u64 sy = swap2(Y[j]);
        X[j] = fma2(c2, X[j], mul2(s2,  sy));
        Y[j] = fma2(c2, Y[j], mul2(sn2, sx));
    }
}

__global__ void __launch_bounds__(NT, 4)
qsim_kernel(const float* __restrict__ x, const float* __restrict__ w,
            float* __restrict__ out) {
    __shared__ float sre[4096];
    __shared__ float sim[4096];
    __shared__ float2 trig[NL + 1][NQ];     // (cos, sin), indexed by logical BIT
    __shared__ float w_acc[NT / 32][NQ];

    const int tid  = threadIdx.x;
    const int lane = tid & 31;
    const int wp   = tid >> 5;
    const int blk  = blockIdx.x;

    if (tid < NQ * (NL + 1)) {
        int l = tid / NQ, q = tid % NQ;
        float th = 0.5f * (l == 0 ? x[blk * NQ + (NQ - 1 - q)]
                                  : w[(l - 1) * NQ + (NQ - 1 - q)]);
        trig[l][q] = make_float2(cosf(th), sinf(th));
    }
    __syncthreads();

    u64 X[8], Y[8];

    // ---- init: product state after input RX layer on |0...0> ----
    {
        float mh = 1.0f;
        #pragma unroll
        for (int b = 0; b < 8; b++) {
            float2 t = trig[0][b + 4];
            mh *= ((tid >> b) & 1) ? t.y : t.x;
        }
        const int pch = __popc(tid);
        const float2 t3 = trig[0][3];
        #pragma unroll
        for (int j = 0; j < 8; j++) {
            float mj = mh;
            #pragma unroll
            for (int b = 0; b < 3; b++) {
                float2 t = trig[0][b];
                mj *= ((j >> b) & 1) ? t.y : t.x;
            }
            float mlo = mj * t3.x, mhi = mj * t3.y;
            int pc  = (pch + __popc(j)) & 3;
            int pc2 = (pc + 1) & 3;
            float relo = (pc  == 0) ?  mlo : (pc  == 2) ? -mlo : 0.0f;
            float imlo = (pc  == 1) ? -mlo : (pc  == 3) ?  mlo : 0.0f;
            float rehi = (pc2 == 0) ?  mhi : (pc2 == 2) ? -mhi : 0.0f;
            float imhi = (pc2 == 1) ? -mhi : (pc2 == 3) ?  mhi : 0.0f;
            X[j] = pack2(relo, rehi);
            Y[j] = pack2(imlo, imhi);
        }
    }

    bool first = true;
    #pragma unroll 1
    for (int l = 1; l <= NL; l++) {
        // ---- frame I: reg bits 0-3 = logical 0-3 ----
        #pragma unroll
        for (int q = 0; q < 4; q++) {
            float2 t = trig[l][q];
            u64 c2 = pack2(t.x, t.x), s2 = pack2(t.y, t.y), sn2 = pack2(-t.y, -t.y);
            if (q == 0) rx_low<0>(X, Y, c2, s2, sn2);
            else if (q == 1) rx_low<1>(X, Y, c2, s2, sn2);
            else if (q == 2) rx_low<2>(X, Y, c2, s2, sn2);
            else rx_b3(X, Y, c2, s2, sn2);
        }

        // ---- T1: swap slot bits 0-3 <-> 4-7 ----
        if (!first) __syncthreads();
        first = false;
        #pragma unroll
        for (int j = 0; j < 8; j++) {
            int a = (j << 8) | (wp << 5) | (lane ^ j);
            float xl, xh, yl, yh;
            unpack2(X[j], xl, xh);
            unpack2(Y[j], yl, yh);
            sre[a] = xl;           sim[a] = yl;
            sre[a ^ 0x808] = xh;   sim[a ^ 0x808] = yh;
        }
        __syncthreads();
        {
            const int g1 = ((lane & 15) << 8) | (wp << 5) | (lane & 16);
            #pragma unroll
            for (int j = 0; j < 8; j++) {
                int a = g1 | (j ^ (lane & 15));
                X[j] = pack2(sre[a], sre[a ^ 8]);
                Y[j] = pack2(sim[a], sim[a ^ 8]);
            }
        }

        // ---- frame f1: reg bits 0-3 = logical 4-7 ----
        #pragma unroll
        for (int q = 0; q < 4; q++) {
            float2 t = trig[l][q + 4];
            u64 c2 = pack2(t.x, t.x), s2 = pack2(t.y, t.y), sn2 = pack2(-t.y, -t.y);
            if (q == 0) rx_low<0>(X, Y, c2, s2, sn2);
            else if (q == 1) rx_low<1>(X, Y, c2, s2, sn2);
            else if (q == 2) rx_low<2>(X, Y, c2, s2, sn2);
            else rx_b3(X, Y, c2, s2, sn2);
        }

        // ---- T2: swap slot bits 0-3 <-> 8-11 ----
        __syncthreads();
        #pragma unroll
        for (int j = 0; j < 8; j++) {
            int a = (j << 8) | (wp << 5) | (lane ^ ((j & 1) << 4));
            float xl, xh, yl, yh;
            unpack2(X[j], xl, xh);
            unpack2(Y[j], yl, yh);
            sre[a] = xl;           sim[a] = yl;
            sre[a ^ 0x800] = xh;   sim[a ^ 0x800] = yh;
        }
        __syncthreads();
        {
            const int g2 = (((lane >> 4) | (wp << 1)) << 8) | (lane & 15)
                         | (((lane >> 4) & 1) << 4);
            #pragma unroll
            for (int j = 0; j < 8; j++) {
                int a = (g2 ^ ((j & 1) << 4)) | ((j >> 1) << 5);
                X[j] = pack2(sre[a], sre[a ^ 0x80]);
                Y[j] = pack2(sim[a], sim[a ^ 0x80]);
            }
        }

        // ---- frame f2: reg bits 0-3 = logical 8-11 ----
        #pragma unroll
        for (int q = 0; q < 4; q++) {
            float2 t = trig[l][q + 8];
            u64 c2 = pack2(t.x, t.x), s2 = pack2(t.y, t.y), sn2 = pack2(-t.y, -t.y);
            if (q == 0) rx_low<0>(X, Y, c2, s2, sn2);
            else if (q == 1) rx_low<1>(X, Y, c2, s2, sn2);
            else if (q == 2) rx_low<2>(X, Y, c2, s2, sn2);
            else rx_b3(X, Y, c2, s2, sn2);
        }

        if (l == 1) {
            // ---- T3: back to frame I with all 12 CNOTs folded ----
            __syncthreads();               // all T2 gathers done before overwrite
            #pragma unroll
            for (int j = 0; j < 8; j++) {
                int a = (j << 8) | (wp << 5) | (lane ^ wp);
                float xl, xh, yl, yh;
                unpack2(X[j], xl, xh);
                unpack2(Y[j], yl, yh);
                sre[a] = xl;           sim[a] = yl;
                sre[a ^ 0x800] = xh;   sim[a ^ 0x800] = yh;
            }
            __syncthreads();
            {
                // addr(P ^ c) = addr(P) ^ A(c): strength-reduce per-j gather.
                const int sb = (wp << 9) | (lane << 4);
                const int P  = ((sb ^ (sb >> 1)) & 0x3FF)
                             | ((((sb >> 10) ^ (sb >> 11) ^ sb) & 1) << 10)
                             | ((((sb >> 11) ^ sb) & 1) << 11);
                const int abase = (P & 0xFE0) | ((P & 31) ^ ((P >> 5) & 7));
                const int AJ[8] = {0x000, 0xC01, 0x003, 0xC02,
                                   0x006, 0xC07, 0x005, 0xC04};
                #pragma unroll
                for (int j = 0; j < 8; j++) {
                    int a = abase ^ AJ[j];
                    X[j] = pack2(sre[a], sre[a ^ 0xC]);
                    Y[j] = pack2(sim[a], sim[a ^ 0xC]);
                }
            }
        }
        // l == 2: stay in frame f2 with pending ring perm; folded below.
    }

    // ---- expectations (frame f2 + pending perm folded into signs) ----
    const u64 one2  = pack2(1.0f, 1.0f);
    const u64 mone2 = pack2(-1.0f, -1.0f);
    u64 Dp, Ep, Fp;
    {
        u64 P = fma2(X[0], X[0], mul2(Y[0], Y[0]));
        Dp = P; Ep = P; Fp = P;
    }
    #pragma unroll
    for (int j = 1; j < 8; j++) {
        u64 P = fma2(X[j], X[j], mul2(Y[j], Y[j]));
        Dp = fma2((__popc(j) & 1) ? mone2 : one2, P, Dp);
        Ep = fma2((((j >> 1) ^ (j >> 2)) & 1) ? mone2 : one2, P, Ep);
        Fp = fma2(((j >> 2) & 1) ? mone2 : one2, P, Fp);
    }
    u64 DG, EF;
    {
        float dlo, dhi, elo, ehi, flo, fhi;
        unpack2(Dp, dlo, dhi);
        unpack2(Ep, elo, ehi);
        unpack2(Fp, flo, fhi);
        DG = pack2(dlo - dhi, dlo + dhi);
        EF = pack2(elo - ehi, flo - fhi);
    }

    // Packed Walsh-Hadamard over the 5 lane bits on (D,G); allreduce on (E,F).
    #pragma unroll
    for (int st = 0; st < 5; st++) {
        const int m = 1 << st;
        u64 tD = __shfl_xor_sync(0xffffffffu, DG, m);
        u64 tE = __shfl_xor_sync(0xffffffffu, EF, m);
        DG = fma2((lane & m) ? mone2 : one2, DG, tD);
        EF = add2(EF, tE);
    }

    {
        float cD, cG, cE, cF;
        unpack2(DG, cD, cG);
        unpack2(EF, cE, cF);
        const int pw = __popc(wp) & 1;
        const float sD = pw ? -cD : cD;
        if (lane == 31) {
            w_acc[wp][0]  = sD;
            w_acc[wp][11] = pw ? -cG : cG;
        } else if (lane == 30) w_acc[wp][1] = sD;
        else if (lane == 28)   w_acc[wp][2] = sD;
        else if (lane == 24)   w_acc[wp][3] = sD;
        else if (lane == 16)   w_acc[wp][4] = sD;
        else if (lane == 0) {
            w_acc[wp][5] = sD;
            w_acc[wp][6] = (((wp >> 1) ^ (wp >> 2)) & 1) ? -cD : cD;
            w_acc[wp][7] = ((wp >> 2) & 1) ? -cD : cD;
            w_acc[wp][8] = cD;
            w_acc[wp][9] = cE;
            w_acc[wp][10] = cF;
        }
    }
    __syncthreads();
    if (tid < NQ) {
        float v = 0.0f;
        #pragma unroll
        for (int wi = 0; wi < NT / 32; wi++) v += w_acc[wi][tid];
        out[blk * NQ + (NQ - 1 - tid)] = v;
    }
}

extern "C" void kernel_launch(void* const* d_in, const int* in_sizes, int n_in,
                              void* d_out, int out_size) {
    const float* x = (const float*)d_in[0];   // (B, 12) float32
    const float* w = (const float*)d_in[1];   // (2, 12) float32
    float* out = (float*)d_out;               // (B, 12) float32
    int B = in_sizes[0] / NQ;
    qsim_kernel<<<B, NT>>>(x, w, out);
}

// round 10
// speedup vs baseline: 1.6503x; 1.6503x over previous
#include <cuda_runtime.h>

#define NQ 12
#define NT 256
#define NL 2

typedef unsigned long long u64;

// ---- packed f32x2 helpers ----
__device__ __forceinline__ u64 pack2(float lo, float hi) {
    u64 v; asm("mov.b64 %0, {%1, %2};" : "=l"(v) : "f"(lo), "f"(hi)); return v;
}
__device__ __forceinline__ void unpack2(u64 v, float &lo, float &hi) {
    asm("mov.b64 {%0, %1}, %2;" : "=f"(lo), "=f"(hi) : "l"(v));
}
__device__ __forceinline__ u64 swap2(u64 v) {
    float lo, hi; unpack2(v, lo, hi); return pack2(hi, lo);
}
__device__ __forceinline__ u64 fma2(u64 a, u64 b, u64 c) {
    u64 d; asm("fma.rn.f32x2 %0, %1, %2, %3;" : "=l"(d) : "l"(a), "l"(b), "l"(c)); return d;
}
__device__ __forceinline__ u64 mul2(u64 a, u64 b) {
    u64 d; asm("mul.rn.f32x2 %0, %1, %2;" : "=l"(d) : "l"(a), "l"(b)); return d;
}
__device__ __forceinline__ u64 add2(u64 a, u64 b) {
    u64 d; asm("add.rn.f32x2 %0, %1, %2;" : "=l"(d) : "l"(a), "l"(b)); return d;
}

// State: X[j] = (re[j], re[j|8]), Y[j] = (im[j], im[j|8]), j = slot bits 0-2,
// packed half = slot bit 3. Slot s = wp*512 + lane*16 + r.
// Reference convention: qubit j <-> logical bit (11-j).
// Variational gates use the tangent form: RX(th) = cos * (I - i tan X); the
// cos factors are accumulated into one global scalar and applied as C^2 to
// the final expectation values.

// Scale-free RX on register bit B in {0,1,2}: new0 = a0 - i t a1, new1 = a1 - i t a0.
template<int B>
__device__ __forceinline__ void rx_low_t(u64 (&X)[8], u64 (&Y)[8],
                                         u64 t2, u64 tn2) {
    #pragma unroll
    for (int j = 0; j < 8; j++) {
        if (!((j >> B) & 1)) {
            const int j1 = j | (1 << B);
            u64 x0 = X[j], x1 = X[j1], y0 = Y[j], y1 = Y[j1];
            X[j]  = fma2(t2,  y1, x0);
            X[j1] = fma2(t2,  y0, x1);
            Y[j]  = fma2(tn2, x1, y0);
            Y[j1] = fma2(tn2, x0, y1);
        }
    }
}

// Scale-free RX on the packed bit (slot bit 3).
__device__ __forceinline__ void rx_b3_t(u64 (&X)[8], u64 (&Y)[8],
                                        u64 t2, u64 tn2) {
    #pragma unroll
    for (int j = 0; j < 8; j++) {
        u64 sx = swap2(X[j]);
        u64 sy = swap2(Y[j]);
        X[j] = fma2(t2,  sy, X[j]);
        Y[j] = fma2(tn2, sx, Y[j]);
    }
}

__global__ void __launch_bounds__(NT, 4)
qsim_kernel(const float* __restrict__ x, const float* __restrict__ w,
            float* __restrict__ out) {
    __shared__ float2 sbuf[4096];
    __shared__ float2 trig[NL + 1][NQ];   // l=0: (cos,sin); l>=1: (tan,-tan)
    __shared__ float cosv[NL * NQ];       // cos(th) of the 24 variational gates
    __shared__ float w_acc[NT / 32][NQ];

    const int tid  = threadIdx.x;
    const int lane = tid & 31;
    const int wp   = tid >> 5;
    const int blk  = blockIdx.x;

    if (tid < NQ * (NL + 1)) {
        int l = tid / NQ, q = tid % NQ;
        if (l == 0) {
            float th = 0.5f * x[blk * NQ + (NQ - 1 - q)];
            trig[0][q] = make_float2(cosf(th), sinf(th));
        } else {
            float th = 0.5f * w[(l - 1) * NQ + (NQ - 1 - q)];
            float c = cosf(th), s = sinf(th);
            float t = s / c;
            trig[l][q] = make_float2(t, -t);
            cosv[(l - 1) * NQ + q] = c;
        }
    }
    __syncthreads();

    u64 X[8], Y[8];

    // ---- init: product state after input RX layer on |0...0> ----
    {
        float mh = 1.0f;
        #pragma unroll
        for (int b = 0; b < 8; b++) {
            float2 t = trig[0][b + 4];
            mh *= ((tid >> b) & 1) ? t.y : t.x;
        }
        const int pch = __popc(tid);
        const float2 t3 = trig[0][3];
        #pragma unroll
        for (int j = 0; j < 8; j++) {
            float mj = mh;
            #pragma unroll
            for (int b = 0; b < 3; b++) {
                float2 t = trig[0][b];
                mj *= ((j >> b) & 1) ? t.y : t.x;
            }
            float mlo = mj * t3.x, mhi = mj * t3.y;
            int pc  = (pch + __popc(j)) & 3;
            int pc2 = (pc + 1) & 3;
            float relo = (pc  == 0) ?  mlo : (pc  == 2) ? -mlo : 0.0f;
            float imlo = (pc  == 1) ? -mlo : (pc  == 3) ?  mlo : 0.0f;
            float rehi = (pc2 == 0) ?  mhi : (pc2 == 2) ? -mhi : 0.0f;
            float imhi = (pc2 == 1) ? -mhi : (pc2 == 3) ?  mhi : 0.0f;
            X[j] = pack2(relo, rehi);
            Y[j] = pack2(imlo, imhi);
        }
    }

    bool first = true;
    #pragma unroll 1
    for (int l = 1; l <= NL; l++) {
        // ---- frame I: reg bits 0-3 = logical 0-3 ----
        #pragma unroll
        for (int q = 0; q < 4; q++) {
            float2 t = trig[l][q];
            u64 t2 = pack2(t.x, t.x), tn2 = pack2(t.y, t.y);
            if (q == 0) rx_low_t<0>(X, Y, t2, tn2);
            else if (q == 1) rx_low_t<1>(X, Y, t2, tn2);
            else if (q == 2) rx_low_t<2>(X, Y, t2, tn2);
            else rx_b3_t(X, Y, t2, tn2);
        }

        // ---- T1: swap slot bits 0-3 <-> 4-7 ----
        if (!first) __syncthreads();
        first = false;
        #pragma unroll
        for (int j = 0; j < 8; j++) {
            float xl, xh, yl, yh;
            unpack2(X[j], xl, xh);
            unpack2(Y[j], yl, yh);
            sbuf[(j << 8) | (wp << 5) | (lane ^ j)]             = make_float2(xl, yl);
            sbuf[((j | 8) << 8) | (wp << 5) | (lane ^ (j | 8))] = make_float2(xh, yh);
        }
        __syncthreads();
        #pragma unroll
        for (int j = 0; j < 8; j++) {
            const int base = ((lane & 15) << 8) | (wp << 5) | (lane & 16);
            float2 t0 = sbuf[base | (j ^ (lane & 15))];
            float2 t1 = sbuf[base | ((j | 8) ^ (lane & 15))];
            X[j] = pack2(t0.x, t1.x);
            Y[j] = pack2(t0.y, t1.y);
        }

        // ---- frame f1: reg bits 0-3 = logical 4-7 ----
        #pragma unroll
        for (int q = 0; q < 4; q++) {
            float2 t = trig[l][q + 4];
            u64 t2 = pack2(t.x, t.x), tn2 = pack2(t.y, t.y);
            if (q == 0) rx_low_t<0>(X, Y, t2, tn2);
            else if (q == 1) rx_low_t<1>(X, Y, t2, tn2);
            else if (q == 2) rx_low_t<2>(X, Y, t2, tn2);
            else rx_b3_t(X, Y, t2, tn2);
        }

        // ---- T2: swap slot bits 0-3 <-> 8-11 ----
        __syncthreads();
        #pragma unroll
        for (int j = 0; j < 8; j++) {
            float xl, xh, yl, yh;
            unpack2(X[j], xl, xh);
            unpack2(Y[j], yl, yh);
            sbuf[(j << 8) | (wp << 5) | (lane ^ ((j & 1) << 4))]       = make_float2(xl, yl);
            sbuf[((j | 8) << 8) | (wp << 5) | (lane ^ ((j & 1) << 4))] = make_float2(xh, yh);
        }
        __syncthreads();
        #pragma unroll
        for (int j = 0; j < 8; j++) {
            const int ru = (lane >> 4) | (wp << 1);
            int r0 = j, r1 = j | 8;
            int a0 = (ru << 8) | ((r0 >> 1) << 5) | (lane & 15)
                   | (((r0 & 1) ^ (lane >> 4)) << 4);
            int a1 = (ru << 8) | ((r1 >> 1) << 5) | (lane & 15)
                   | (((r1 & 1) ^ (lane >> 4)) << 4);
            float2 t0 = sbuf[a0];
            float2 t1 = sbuf[a1];
            X[j] = pack2(t0.x, t1.x);
            Y[j] = pack2(t0.y, t1.y);
        }

        // ---- frame f2: reg bits 0-3 = logical 8-11 ----
        #pragma unroll
        for (int q = 0; q < 4; q++) {
            float2 t = trig[l][q + 8];
            u64 t2 = pack2(t.x, t.x), tn2 = pack2(t.y, t.y);
            if (q == 0) rx_low_t<0>(X, Y, t2, tn2);
            else if (q == 1) rx_low_t<1>(X, Y, t2, tn2);
            else if (q == 2) rx_low_t<2>(X, Y, t2, tn2);
            else rx_b3_t(X, Y, t2, tn2);
        }

        if (l == 1) {
            // ---- T3: back to frame I with all 12 CNOTs folded ----
            __syncthreads();
            #pragma unroll
            for (int j = 0; j < 8; j++) {
                float xl, xh, yl, yh;
                unpack2(X[j], xl, xh);
                unpack2(Y[j], yl, yh);
                sbuf[(j << 8) | (wp << 5) | (lane ^ wp)]       = make_float2(xl, yl);
                sbuf[((j | 8) << 8) | (wp << 5) | (lane ^ wp)] = make_float2(xh, yh);
            }
            __syncthreads();
            #pragma unroll
            for (int j = 0; j < 8; j++) {
                float v[2][2];
                #pragma unroll
                for (int h = 0; h < 2; h++) {
                    int r = j | (h << 3);
                    int s  = (wp << 9) | (lane << 4) | r;
                    int P  = ((s ^ (s >> 1)) & 0x3FF)
                           | ((((s >> 10) ^ (s >> 11) ^ s) & 1) << 10)
                           | ((((s >> 11) ^ s) & 1) << 11);
                    int ru = P >> 8;
                    int wu = (P >> 5) & 7;
                    int lu = P & 31;
                    float2 t = sbuf[(ru << 8) | (wu << 5) | (lu ^ wu)];
                    v[h][0] = t.x; v[h][1] = t.y;
                }
                X[j] = pack2(v[0][0], v[1][0]);
                Y[j] = pack2(v[0][1], v[1][1]);
            }
        }
        // l == 2: stay in frame f2 with pending ring perm; folded below.
    }

    // ---- expectations (frame f2 + pending perm folded into signs) ----
    const u64 one2  = pack2(1.0f, 1.0f);
    const u64 mone2 = pack2(-1.0f, -1.0f);
    u64 Dp, Ep, Fp;
    {
        u64 P = fma2(X[0], X[0], mul2(Y[0], Y[0]));
        Dp = P; Ep = P; Fp = P;
    }
    #pragma unroll
    for (int j = 1; j < 8; j++) {
        u64 P = fma2(X[j], X[j], mul2(Y[j], Y[j]));
        Dp = fma2((__popc(j) & 1) ? mone2 : one2, P, Dp);
        Ep = fma2((((j >> 1) ^ (j >> 2)) & 1) ? mone2 : one2, P, Ep);
        Fp = fma2(((j >> 2) & 1) ? mone2 : one2, P, Fp);
    }
    u64 DG, EF;
    {
        float dlo, dhi, elo, ehi, flo, fhi;
        unpack2(Dp, dlo, dhi);
        unpack2(Ep, elo, ehi);
        unpack2(Fp, flo, fhi);
        DG = pack2(dlo - dhi, dlo + dhi);
        EF = pack2(elo - ehi, flo - fhi);
    }

    // Packed Walsh-Hadamard over the 5 lane bits on (D,G); allreduce on (E,F).
    #pragma unroll
    for (int st = 0; st < 5; st++) {
        const int m = 1 << st;
        u64 tD = __shfl_xor_sync(0xffffffffu, DG, m);
        u64 tE = __shfl_xor_sync(0xffffffffu, EF, m);
        DG = fma2((lane & m) ? mone2 : one2, DG, tD);
        EF = add2(EF, tE);
    }

    {
        float cD, cG, cE, cF;
        unpack2(DG, cD, cG);
        unpack2(EF, cE, cF);
        const int pw = __popc(wp) & 1;
        const float sD = pw ? -cD : cD;
        if (lane == 31) {
            w_acc[wp][0]  = sD;
            w_acc[wp][11] = pw ? -cG : cG;
        } else if (lane == 30) w_acc[wp][1] = sD;
        else if (lane == 28)   w_acc[wp][2] = sD;
        else if (lane == 24)   w_acc[wp][3] = sD;
        else if (lane == 16)   w_acc[wp][4] = sD;
        else if (lane == 0) {
            w_acc[wp][5] = sD;
            w_acc[wp][6] = (((wp >> 1) ^ (wp >> 2)) & 1) ? -cD : cD;
            w_acc[wp][7] = ((wp >> 2) & 1) ? -cD : cD;
            w_acc[wp][8] = cD;
            w_acc[wp][9] = cE;
            w_acc[wp][10] = cF;
        }
    }
    __syncthreads();
    if (tid < NQ) {
        float v = 0.0f;
        #pragma unroll
        for (int wi = 0; wi < NT / 32; wi++) v += w_acc[wi][tid];
        // apply the deferred cos factors: outputs scale by C^2
        float C = 1.0f;
        #pragma unroll
        for (int g = 0; g < NL * NQ; g++) C *= cosv[g];
        out[blk * NQ + (NQ - 1 - tid)] = v * (C * C);
    }
}

extern "C" void kernel_launch(void* const* d_in, const int* in_sizes, int n_in,
                              void* d_out, int out_size) {
    const float* x = (const float*)d_in[0];   // (B, 12) float32
    const float* w = (const float*)d_in[1];   // (2, 12) float32
    float* out = (float*)d_out;               // (B, 12) float32
    int B = in_sizes[0] / NQ;
    qsim_kernel<<<B, NT>>>(x, w, out);
}

// round 11
// speedup vs baseline: 1.7301x; 1.0483x over previous
#include <cuda_runtime.h>

#define NQ 12
#define NT 256

typedef unsigned long long u64;

// ---- packed f32x2 helpers ----
static __device__ __forceinline__ u64 pack2(float lo, float hi) {
    u64 v; asm("mov.b64 %0, {%1, %2};" : "=l"(v) : "f"(lo), "f"(hi)); return v;
}
static __device__ __forceinline__ void unpack2(u64 v, float &lo, float &hi) {
    asm("mov.b64 {%0, %1}, %2;" : "=f"(lo), "=f"(hi) : "l"(v));
}
static __device__ __forceinline__ u64 fma2(u64 a, u64 b, u64 c) {
    u64 d; asm("fma.rn.f32x2 %0, %1, %2, %3;" : "=l"(d) : "l"(a), "l"(b), "l"(c)); return d;
}
static __device__ __forceinline__ u64 mul2(u64 a, u64 b) {
    u64 d; asm("mul.rn.f32x2 %0, %1, %2;" : "=l"(d) : "l"(a), "l"(b)); return d;
}
static __device__ __forceinline__ u64 add2(u64 a, u64 b) {
    u64 d; asm("add.rn.f32x2 %0, %1, %2;" : "=l"(d) : "l"(a), "l"(b)); return d;
}

// One CTA simulates TWO batch elements: lo half of every u64 = element A,
// hi half = element B. Per element: slot s = wp*512 + lane*16 + r, r = 4-bit
// register index (16 amps/thread/element). Qubit j <-> logical bit (11-j).
// Variational gates use RX(th) = cos * (I - i tan X); the cos product C is
// applied as C^2 to the outputs (identical for both elements since w shared).

template<int B>
__device__ __forceinline__ void rx16(u64 (&X)[16], u64 (&Y)[16], u64 t2, u64 tn2) {
    #pragma unroll
    for (int j = 0; j < 16; j++) {
        if (!((j >> B) & 1)) {
            const int j1 = j | (1 << B);
            u64 x0 = X[j], x1 = X[j1], y0 = Y[j], y1 = Y[j1];
            X[j]  = fma2(t2,  y1, x0);
            X[j1] = fma2(t2,  y0, x1);
            Y[j]  = fma2(tn2, x1, y0);
            Y[j1] = fma2(tn2, x0, y1);
        }
    }
}

__device__ __forceinline__ void frame4(u64 (&X)[16], u64 (&Y)[16], const float2* t) {
    #pragma unroll
    for (int q = 0; q < 4; q++) {
        float2 tq = t[q];                       // (tan, -tan)
        u64 t2 = pack2(tq.x, tq.x), tn2 = pack2(tq.y, tq.y);
        if (q == 0) rx16<0>(X, Y, t2, tn2);
        else if (q == 1) rx16<1>(X, Y, t2, tn2);
        else if (q == 2) rx16<2>(X, Y, t2, tn2);
        else rx16<3>(X, Y, t2, tn2);
    }
}

__global__ void __launch_bounds__(NT, 2)
qsim_kernel(const float* __restrict__ x, const float* __restrict__ w,
            float* __restrict__ out) {
    extern __shared__ __align__(16) char dsm[];
    u64*    sbX   = reinterpret_cast<u64*>(dsm);          // [4096] 32 KB
    u64*    sbY   = sbX + 4096;                           // [4096] 32 KB
    float2* trig0 = reinterpret_cast<float2*>(sbY + 4096);// [2][12] (cos,sin)
    float2* tl    = trig0 + 24;                           // [2][12] (tan,-tan)
    float*  cosv  = reinterpret_cast<float*>(tl + 24);    // [24]
    float*  wacc  = cosv + 24;                            // [2][8][12]

    const int tid  = threadIdx.x;
    const int lane = tid & 31;
    const int wp   = tid >> 5;
    const int blk  = blockIdx.x;

    if (tid < 24) {
        int e = tid / 12, q = tid % 12;
        float th = 0.5f * x[(2 * blk + e) * NQ + (NQ - 1 - q)];
        trig0[e * 12 + q] = make_float2(cosf(th), sinf(th));
    } else if (tid < 48) {
        int t = tid - 24, l = t / 12, q = t % 12;
        float th = 0.5f * w[l * NQ + (NQ - 1 - q)];
        float c = cosf(th), s = sinf(th), tn = s / c;
        tl[l * 12 + q] = make_float2(tn, -tn);
        cosv[t] = c;
    }
    __syncthreads();

    u64 X[16], Y[16];

    // ---- init: product state after input RX layer on |0...0>, per element ----
    {
        float mhA = 1.0f, mhB = 1.0f;
        #pragma unroll
        for (int b = 0; b < 8; b++) {
            float2 tA = trig0[b + 4], tB = trig0[12 + b + 4];
            bool bit = (tid >> b) & 1;
            mhA *= bit ? tA.y : tA.x;
            mhB *= bit ? tB.y : tB.x;
        }
        const int pch = __popc(tid);
        #pragma unroll
        for (int j = 0; j < 16; j++) {
            float mA = mhA, mB = mhB;
            #pragma unroll
            for (int b = 0; b < 4; b++) {
                float2 tA = trig0[b], tB = trig0[12 + b];
                bool bit = (j >> b) & 1;
                mA *= bit ? tA.y : tA.x;
                mB *= bit ? tB.y : tB.x;
            }
            int pc = (pch + __popc(j)) & 3;
            float reA = (pc == 0) ?  mA : (pc == 2) ? -mA : 0.0f;
            float imA = (pc == 1) ? -mA : (pc == 3) ?  mA : 0.0f;
            float reB = (pc == 0) ?  mB : (pc == 2) ? -mB : 0.0f;
            float imB = (pc == 1) ? -mB : (pc == 3) ?  mB : 0.0f;
            X[j] = pack2(reA, reB);
            Y[j] = pack2(imA, imB);
        }
    }

    #pragma unroll 1
    for (int l = 0; l < 2; l++) {
        // frame I: regs = logical 0-3
        frame4(X, Y, &tl[l * 12]);

        // ---- T1: swap slot bits 0-3 <-> 4-7 ----
        if (l) __syncthreads();            // layer-1 T3 gathers crossed stripes
        #pragma unroll
        for (int j = 0; j < 16; j++) {
            int a = (j << 8) | (wp << 5) | (lane ^ j);
            sbX[a] = X[j];
            sbY[a] = Y[j];
        }
        __syncthreads();
        {
            const int g = ((lane & 15) << 8) | (wp << 5) | (lane & 16);
            #pragma unroll
            for (int j = 0; j < 16; j++) {
                int a = g | (j ^ (lane & 15));
                X[j] = sbX[a];
                Y[j] = sbY[a];
            }
        }

        // frame f1: regs = logical 4-7
        frame4(X, Y, &tl[l * 12 + 4]);

        // ---- T2: swap slot bits 0-3 <-> 8-11 ----
        __syncwarp();                      // T1 gather (own stripe) before overwrite
        #pragma unroll
        for (int j = 0; j < 16; j++) {
            int a = (j << 8) | (wp << 5) | (lane ^ ((j & 1) << 4));
            sbX[a] = X[j];
            sbY[a] = Y[j];
        }
        __syncthreads();
        {
            const int ru = (lane >> 4) | (wp << 1);
            #pragma unroll
            for (int j = 0; j < 16; j++) {
                int a = (ru << 8) | ((j >> 1) << 5) | (lane & 15)
                      | (((j & 1) ^ (lane >> 4)) << 4);
                X[j] = sbX[a];
                Y[j] = sbY[a];
            }
        }

        // frame f2: regs = logical 8-11
        frame4(X, Y, &tl[l * 12 + 8]);

        if (l == 0) {
            // ---- T3: back to frame I with all 12 CNOTs folded ----
            __syncthreads();               // all T2 gathers done before overwrite
            #pragma unroll
            for (int j = 0; j < 16; j++) {
                int a = (j << 8) | (wp << 5) | (lane ^ wp);
                sbX[a] = X[j];
                sbY[a] = Y[j];
            }
            __syncthreads();
            #pragma unroll
            for (int j = 0; j < 16; j++) {
                int s = (wp << 9) | (lane << 4) | j;
                int P = ((s ^ (s >> 1)) & 0x3FF)
                      | ((((s >> 10) ^ (s >> 11) ^ s) & 1) << 10)
                      | ((((s >> 11) ^ s) & 1) << 11);
                int a = (P & 0xF00) | (((P >> 5) & 7) << 5)
                      | ((P & 31) ^ ((P >> 5) & 7));
                X[j] = sbX[a];
                Y[j] = sbY[a];
            }
        }
        // l == 1: stay in frame f2 with pending ring perm; folded below.
    }

    // ---- expectations (frame f2 + pending perm folded into signs) ----
    const u64 one2  = pack2(1.0f, 1.0f);
    const u64 mone2 = pack2(-1.0f, -1.0f);
    u64 Dp, Ep, Fp, Gp;
    {
        u64 P0 = fma2(X[0], X[0], mul2(Y[0], Y[0]));
        Dp = P0; Ep = P0; Fp = P0; Gp = P0;
    }
    #pragma unroll
    for (int j = 1; j < 16; j++) {
        u64 P = fma2(X[j], X[j], mul2(Y[j], Y[j]));
        Dp = fma2((__popc(j)      & 1) ? mone2 : one2, P, Dp);  // r0^r1^r2^r3
        Ep = fma2((__popc(j & 14) & 1) ? mone2 : one2, P, Ep);  // r1^r2^r3
        Fp = fma2((__popc(j & 12) & 1) ? mone2 : one2, P, Fp);  // r2^r3
        Gp = fma2((__popc(j & 7)  & 1) ? mone2 : one2, P, Gp);  // r0^r1^r2
    }

    // Walsh-Hadamard over the 5 lane bits on D and G; allreduce on E, F.
    #pragma unroll
    for (int st = 0; st < 5; st++) {
        const int m = 1 << st;
        u64 sD = __shfl_xor_sync(0xffffffffu, Dp, m);
        u64 sG = __shfl_xor_sync(0xffffffffu, Gp, m);
        u64 sE = __shfl_xor_sync(0xffffffffu, Ep, m);
        u64 sF = __shfl_xor_sync(0xffffffffu, Fp, m);
        u64 sgn = (lane & m) ? mone2 : one2;
        Dp = fma2(sgn, Dp, sD);
        Gp = fma2(sgn, Gp, sG);
        Ep = add2(Ep, sE);
        Fp = add2(Fp, sF);
    }

    {
        float dA, dB, gA, gB, eA, eB, fA, fB;
        unpack2(Dp, dA, dB);
        unpack2(Gp, gA, gB);
        unpack2(Ep, eA, eB);
        unpack2(Fp, fA, fB);
        const int pw = __popc(wp) & 1;
        float sDA = pw ? -dA : dA, sDB = pw ? -dB : dB;
        float* WA = &wacc[wp * 12];
        float* WB = &wacc[96 + wp * 12];
        if (lane == 31) {
            WA[0] = sDA;  WB[0] = sDB;
            WA[11] = pw ? -gA : gA;  WB[11] = pw ? -gB : gB;
        } else if (lane == 30) { WA[1] = sDA; WB[1] = sDB; }
        else if (lane == 28)   { WA[2] = sDA; WB[2] = sDB; }
        else if (lane == 24)   { WA[3] = sDA; WB[3] = sDB; }
        else if (lane == 16)   { WA[4] = sDA; WB[4] = sDB; }
        else if (lane == 0) {
            WA[5] = sDA;  WB[5] = sDB;
            int g6 = ((wp >> 1) ^ (wp >> 2)) & 1;
            WA[6] = g6 ? -dA : dA;  WB[6] = g6 ? -dB : dB;
            int g7 = (wp >> 2) & 1;
            WA[7] = g7 ? -dA : dA;  WB[7] = g7 ? -dB : dB;
            WA[8] = dA;  WB[8] = dB;
            WA[9] = eA;  WB[9] = eB;
            WA[10] = fA; WB[10] = fB;
        }
    }
    __syncthreads();
    if (tid < 24) {
        int e = tid / 12, q = tid % 12;
        float v = 0.0f;
        #pragma unroll
        for (int wi = 0; wi < 8; wi++) v += wacc[e * 96 + wi * 12 + q];
        float C = 1.0f;
        #pragma unroll
        for (int g = 0; g < 24; g++) C *= cosv[g];
        out[(2 * blk + e) * NQ + (NQ - 1 - q)] = v * (C * C);
    }
}

extern "C" void kernel_launch(void* const* d_in, const int* in_sizes, int n_in,
                              void* d_out, int out_size) {
    const float* x = (const float*)d_in[0];   // (B, 12) float32
    const float* w = (const float*)d_in[1];   // (2, 12) float32
    float* out = (float*)d_out;               // (B, 12) float32
    int B = in_sizes[0] / NQ;
    const int smem = 4096 * 8 * 2 + 24 * 8 * 2 + 24 * 4 + 2 * 8 * 12 * 4;
    cudaFuncSetAttribute(qsim_kernel, cudaFuncAttributeMaxDynamicSharedMemorySize, smem);
    qsim_kernel<<<B / 2, NT, smem>>>(x, w, out);
}

// round 12
// speedup vs baseline: 1.9332x; 1.1174x over previous
#include <cuda_runtime.h>

#define NQ 12
#define NT 256

typedef unsigned long long u64;

// ---- packed f32x2 helpers ----
static __device__ __forceinline__ u64 pack2(float lo, float hi) {
    u64 v; asm("mov.b64 %0, {%1, %2};" : "=l"(v) : "f"(lo), "f"(hi)); return v;
}
static __device__ __forceinline__ void unpack2(u64 v, float &lo, float &hi) {
    asm("mov.b64 {%0, %1}, %2;" : "=f"(lo), "=f"(hi) : "l"(v));
}
static __device__ __forceinline__ u64 fma2(u64 a, u64 b, u64 c) {
    u64 d; asm("fma.rn.f32x2 %0, %1, %2, %3;" : "=l"(d) : "l"(a), "l"(b), "l"(c)); return d;
}
static __device__ __forceinline__ u64 mul2(u64 a, u64 b) {
    u64 d; asm("mul.rn.f32x2 %0, %1, %2;" : "=l"(d) : "l"(a), "l"(b)); return d;
}
static __device__ __forceinline__ u64 add2(u64 a, u64 b) {
    u64 d; asm("add.rn.f32x2 %0, %1, %2;" : "=l"(d) : "l"(a), "l"(b)); return d;
}

// One CTA simulates TWO batch elements: lo half of every u64 = element A,
// hi half = element B. Per element: slot s = wp*512 + lane*16 + r, r = 4-bit
// register index (16 amps/thread/element). Qubit j <-> logical bit (11-j).
// Variational gates use RX(th) = cos * (I - i tan X); the cos product C is
// applied as C^2 to the outputs (identical for both elements since w shared).

template<int B>
__device__ __forceinline__ void rx16(u64 (&X)[16], u64 (&Y)[16], u64 t2, u64 tn2) {
    #pragma unroll
    for (int j = 0; j < 16; j++) {
        if (!((j >> B) & 1)) {
            const int j1 = j | (1 << B);
            u64 x0 = X[j], x1 = X[j1], y0 = Y[j], y1 = Y[j1];
            X[j]  = fma2(t2,  y1, x0);
            X[j1] = fma2(t2,  y0, x1);
            Y[j]  = fma2(tn2, x1, y0);
            Y[j1] = fma2(tn2, x0, y1);
        }
    }
}

__device__ __forceinline__ void frame4(u64 (&X)[16], u64 (&Y)[16], const float2* t) {
    #pragma unroll
    for (int q = 0; q < 4; q++) {
        float2 tq = t[q];                       // (tan, -tan)
        u64 t2 = pack2(tq.x, tq.x), tn2 = pack2(tq.y, tq.y);
        if (q == 0) rx16<0>(X, Y, t2, tn2);
        else if (q == 1) rx16<1>(X, Y, t2, tn2);
        else if (q == 2) rx16<2>(X, Y, t2, tn2);
        else rx16<3>(X, Y, t2, tn2);
    }
}

__global__ void __launch_bounds__(NT, 3)
qsim_kernel(const float* __restrict__ x, const float* __restrict__ w,
            float* __restrict__ out) {
    extern __shared__ __align__(16) char dsm[];
    u64*    sbX   = reinterpret_cast<u64*>(dsm);          // [4096] 32 KB
    u64*    sbY   = sbX + 4096;                           // [4096] 32 KB
    float2* trig0 = reinterpret_cast<float2*>(sbY + 4096);// [2][12] (cos,sin)
    float2* tl    = trig0 + 24;                           // [2][12] (tan,-tan)
    float*  cosv  = reinterpret_cast<float*>(tl + 24);    // [24]
    float*  wacc  = cosv + 24;                            // [2][8][12]

    const int tid  = threadIdx.x;
    const int lane = tid & 31;
    const int wp   = tid >> 5;
    const int blk  = blockIdx.x;

    if (tid < 24) {
        int e = tid / 12, q = tid % 12;
        float th = 0.5f * x[(2 * blk + e) * NQ + (NQ - 1 - q)];
        trig0[e * 12 + q] = make_float2(cosf(th), sinf(th));
    } else if (tid < 48) {
        int t = tid - 24, l = t / 12, q = t % 12;
        float th = 0.5f * w[l * NQ + (NQ - 1 - q)];
        float c = cosf(th), s = sinf(th), tn = s / c;
        tl[l * 12 + q] = make_float2(tn, -tn);
        cosv[t] = c;
    }
    __syncthreads();

    u64 X[16], Y[16];

    // ---- init: product state after input RX layer on |0...0>, per element ----
    {
        float mhA = 1.0f, mhB = 1.0f;
        #pragma unroll
        for (int b = 0; b < 8; b++) {
            float2 tA = trig0[b + 4], tB = trig0[12 + b + 4];
            bool bit = (tid >> b) & 1;
            mhA *= bit ? tA.y : tA.x;
            mhB *= bit ? tB.y : tB.x;
        }
        const int pch = __popc(tid);
        #pragma unroll
        for (int j = 0; j < 16; j++) {
            float mA = mhA, mB = mhB;
            #pragma unroll
            for (int b = 0; b < 4; b++) {
                float2 tA = trig0[b], tB = trig0[12 + b];
                bool bit = (j >> b) & 1;
                mA *= bit ? tA.y : tA.x;
                mB *= bit ? tB.y : tB.x;
            }
            int pc = (pch + __popc(j)) & 3;
            float reA = (pc == 0) ?  mA : (pc == 2) ? -mA : 0.0f;
            float imA = (pc == 1) ? -mA : (pc == 3) ?  mA : 0.0f;
            float reB = (pc == 0) ?  mB : (pc == 2) ? -mB : 0.0f;
            float imB = (pc == 1) ? -mB : (pc == 3) ?  mB : 0.0f;
            X[j] = pack2(reA, reB);
            Y[j] = pack2(imA, imB);
        }
    }

    #pragma unroll 1
    for (int l = 0; l < 2; l++) {
        // frame I: regs = logical 0-3
        frame4(X, Y, &tl[l * 12]);

        // ---- T1: swap slot bits 0-3 <-> 4-7 (warp-local: stripe bits 5-7 = wp) ----
        if (l) __syncthreads();            // layer-1 T3 gathers crossed stripes
        #pragma unroll
        for (int j = 0; j < 16; j++) {
            int a = (j << 8) | (wp << 5) | (lane ^ j);
            sbX[a] = X[j];
            sbY[a] = Y[j];
        }
        __syncwarp();
        {
            const int g = ((lane & 15) << 8) | (wp << 5) | (lane & 16);
            #pragma unroll
            for (int j = 0; j < 16; j++) {
                int a = g | (j ^ (lane & 15));
                X[j] = sbX[a];
                Y[j] = sbY[a];
            }
        }

        // frame f1: regs = logical 4-7
        frame4(X, Y, &tl[l * 12 + 4]);

        // ---- T2: swap slot bits 0-3 <-> 8-11 ----
        __syncwarp();                      // T1 gather (own stripe) before overwrite
        #pragma unroll
        for (int j = 0; j < 16; j++) {
            int a = (j << 8) | (wp << 5) | (lane ^ ((j & 1) << 4));
            sbX[a] = X[j];
            sbY[a] = Y[j];
        }
        __syncthreads();
        {
            const int ru = (lane >> 4) | (wp << 1);
            #pragma unroll
            for (int j = 0; j < 16; j++) {
                int a = (ru << 8) | ((j >> 1) << 5) | (lane & 15)
                      | (((j & 1) ^ (lane >> 4)) << 4);
                X[j] = sbX[a];
                Y[j] = sbY[a];
            }
        }

        // frame f2: regs = logical 8-11
        frame4(X, Y, &tl[l * 12 + 8]);

        if (l == 0) {
            // ---- T3: back to frame I with all 12 CNOTs folded ----
            __syncthreads();               // all T2 gathers done before overwrite
            #pragma unroll
            for (int j = 0; j < 16; j++) {
                int a = (j << 8) | (wp << 5) | (lane ^ wp);
                sbX[a] = X[j];
                sbY[a] = Y[j];
            }
            __syncthreads();
            #pragma unroll
            for (int j = 0; j < 16; j++) {
                int s = (wp << 9) | (lane << 4) | j;
                int P = ((s ^ (s >> 1)) & 0x3FF)
                      | ((((s >> 10) ^ (s >> 11) ^ s) & 1) << 10)
                      | ((((s >> 11) ^ s) & 1) << 11);
                int a = (P & 0xF00) | (((P >> 5) & 7) << 5)
                      | ((P & 31) ^ ((P >> 5) & 7));
                X[j] = sbX[a];
                Y[j] = sbY[a];
            }
        }
        // l == 1: stay in frame f2 with pending ring perm; folded below.
    }

    // ---- expectations (frame f2 + pending perm folded into signs) ----
    const u64 one2  = pack2(1.0f, 1.0f);
    const u64 mone2 = pack2(-1.0f, -1.0f);
    u64 Dp, Ep, Fp, Gp;
    {
        u64 P0 = fma2(X[0], X[0], mul2(Y[0], Y[0]));
        Dp = P0; Ep = P0; Fp = P0; Gp = P0;
    }
    #pragma unroll
    for (int j = 1; j < 16; j++) {
        u64 P = fma2(X[j], X[j], mul2(Y[j], Y[j]));
        Dp = fma2((__popc(j)      & 1) ? mone2 : one2, P, Dp);  // r0^r1^r2^r3
        Ep = fma2((__popc(j & 14) & 1) ? mone2 : one2, P, Ep);  // r1^r2^r3
        Fp = fma2((__popc(j & 12) & 1) ? mone2 : one2, P, Fp);  // r2^r3
        Gp = fma2((__popc(j & 7)  & 1) ? mone2 : one2, P, Gp);  // r0^r1^r2
    }

    // Walsh-Hadamard over the 5 lane bits on D and G; allreduce on E, F.
    #pragma unroll
    for (int st = 0; st < 5; st++) {
        const int m = 1 << st;
        u64 sD = __shfl_xor_sync(0xffffffffu, Dp, m);
        u64 sG = __shfl_xor_sync(0xffffffffu, Gp, m);
        u64 sE = __shfl_xor_sync(0xffffffffu, Ep, m);
        u64 sF = __shfl_xor_sync(0xffffffffu, Fp, m);
        u64 sgn = (lane & m) ? mone2 : one2;
        Dp = fma2(sgn, Dp, sD);
        Gp = fma2(sgn, Gp, sG);
        Ep = add2(Ep, sE);
        Fp = add2(Fp, sF);
    }

    {
        float dA, dB, gA, gB, eA, eB, fA, fB;
        unpack2(Dp, dA, dB);
        unpack2(Gp, gA, gB);
        unpack2(Ep, eA, eB);
        unpack2(Fp, fA, fB);
        const int pw = __popc(wp) & 1;
        float sDA = pw ? -dA : dA, sDB = pw ? -dB : dB;
        float* WA = &wacc[wp * 12];
        float* WB = &wacc[96 + wp * 12];
        if (lane == 31) {
            WA[0] = sDA;  WB[0] = sDB;
            WA[11] = pw ? -gA : gA;  WB[11] = pw ? -gB : gB;
        } else if (lane == 30) { WA[1] = sDA; WB[1] = sDB; }
        else if (lane == 28)   { WA[2] = sDA; WB[2] = sDB; }
        else if (lane == 24)   { WA[3] = sDA; WB[3] = sDB; }
        else if (lane == 16)   { WA[4] = sDA; WB[4] = sDB; }
        else if (lane == 0) {
            WA[5] = sDA;  WB[5] = sDB;
            int g6 = ((wp >> 1) ^ (wp >> 2)) & 1;
            WA[6] = g6 ? -dA : dA;  WB[6] = g6 ? -dB : dB;
            int g7 = (wp >> 2) & 1;
            WA[7] = g7 ? -dA : dA;  WB[7] = g7 ? -dB : dB;
            WA[8] = dA;  WB[8] = dB;
            WA[9] = eA;  WB[9] = eB;
            WA[10] = fA; WB[10] = fB;
        }
    }
    __syncthreads();
    if (tid < 24) {
        int e = tid / 12, q = tid % 12;
        float v = 0.0f;
        #pragma unroll
        for (int wi = 0; wi < 8; wi++) v += wacc[e * 96 + wi * 12 + q];
        float C = 1.0f;
        #pragma unroll
        for (int g = 0; g < 24; g++) C *= cosv[g];
        out[(2 * blk + e) * NQ + (NQ - 1 - q)] = v * (C * C);
    }
}

extern "C" void kernel_launch(void* const* d_in, const int* in_sizes, int n_in,
                              void* d_out, int out_size) {
    const float* x = (const float*)d_in[0];   // (B, 12) float32
    const float* w = (const float*)d_in[1];   // (2, 12) float32
    float* out = (float*)d_out;               // (B, 12) float32
    int B = in_sizes[0] / NQ;
    const int smem = 4096 * 8 * 2 + 24 * 8 * 2 + 24 * 4 + 2 * 8 * 12 * 4;
    cudaFuncSetAttribute(qsim_kernel, cudaFuncAttributeMaxDynamicSharedMemorySize, smem);
    qsim_kernel<<<B / 2, NT, smem>>>(x, w, out);
}